// round 2
// baseline (speedup 1.0000x reference)
#include <cuda_runtime.h>
#include <cstdint>

// ---------------- problem constants ----------------
#define D_MODEL 1024
#define Hh      16
#define Nn      4
#define NSKEW   6
#define Bb      4
#define Tt      4096
#define NROWS   (Bb*Tt)                    // 16384
#define NCOLS1  (Hh*NSKEW + Hh*Nn)         // 160
#define VOFF    (Hh*NSKEW)                 // 96
#define HN      (Hh*Nn)                    // 64
#define CHAINS  (Bb*Hh)                    // 64
#define CHUNK   32
#define NCHUNK  (Tt/CHUNK)                 // 128

// ---------------- scratch ----------------
__device__ float g_Wcat[D_MODEL*NCOLS1];
__device__ float g_SV  [NROWS*NCOLS1];
__device__ float g_R   [CHAINS*Tt*16];
__device__ float g_L   [CHAINS*Tt*16];
__device__ float g_Ctot[CHAINS*NCHUNK*16];
__device__ float g_Pprev[CHAINS*NCHUNK*16];
__device__ float g_Rot [NROWS*HN];

// ---------------- tf32 helpers ----------------
__device__ __forceinline__ void tf32_split(float v, uint32_t& hi, uint32_t& lo) {
    uint32_t h;
    asm("cvt.rna.tf32.f32 %0, %1;" : "=r"(h) : "f"(v));
    float r = v - __uint_as_float(h);
    uint32_t l;
    asm("cvt.rna.tf32.f32 %0, %1;" : "=r"(l) : "f"(r));
    hi = h; lo = l;
}

__device__ __forceinline__ void mma_tf32(float* c,
                                         uint32_t a0, uint32_t a1, uint32_t a2, uint32_t a3,
                                         uint32_t b0, uint32_t b1) {
    asm volatile(
        "mma.sync.aligned.m16n8k8.row.col.f32.tf32.tf32.f32 "
        "{%0,%1,%2,%3}, {%4,%5,%6,%7}, {%8,%9}, {%0,%1,%2,%3};"
        : "+f"(c[0]), "+f"(c[1]), "+f"(c[2]), "+f"(c[3])
        : "r"(a0), "r"(a1), "r"(a2), "r"(a3), "r"(b0), "r"(b1));
}

// ---------------- K0: concat weights ----------------
__global__ void concat_w_kernel(const float* __restrict__ Wskew,
                                const float* __restrict__ Wv) {
    int i = blockIdx.x*blockDim.x + threadIdx.x;
    if (i >= D_MODEL*NCOLS1) return;
    int k = i / NCOLS1, c = i % NCOLS1;
    g_Wcat[i] = (c < VOFF) ? Wskew[k*VOFF + c] : Wv[k*HN + (c - VOFF)];
}

// ---------------- split-tf32 tensor-core GEMM ----------------
// C[M,N] = A[M,K] @ B[K,N], all row-major fp32. BM=128, BK=16, 256 threads.
// Precision: 2-way tf32 split (AhiBhi + AloBhi + AhiBlo) ~ fp32 accuracy.
template<int N, int K, int BN>
__global__ void __launch_bounds__(256) gemm_tf32_kernel(const float* __restrict__ A,
                                                        const float* __restrict__ B,
                                                        float* __restrict__ C) {
    constexpr int BM = 128, BK = 16;
    constexpr int WARPS_N = BN/32;        // 1 (BN=32) or 2 (BN=64)
    constexpr int WARPS_M = 8/WARPS_N;    // 8 or 4
    constexpr int WM = BM/WARPS_M;        // 16 or 32
    constexpr int MT = WM/16;             // 1 or 2
    constexpr int NT = 4;                 // 32 cols / n8
    constexpr int AP = BK + 4;            // 20 (bank-conflict-free frag loads)
    constexpr int BP = BN + 4;

    __shared__ uint32_t As[2][BM][AP];    // [hi/lo][m][k]
    __shared__ uint32_t Bs[2][BK][BP];    // [hi/lo][k][n]

    const int tid  = threadIdx.x;
    const int warp = tid >> 5;
    const int lane = tid & 31;
    const int brow = blockIdx.y * BM;
    const int bcol = blockIdx.x * BN;
    const int wm0  = (warp / WARPS_N) * WM;
    const int wn0  = (warp % WARPS_N) * 32;
    const int lr   = lane >> 2;           // 0..7
    const int lc   = lane & 3;            // 0..3

    float acc[MT][NT][4];
    #pragma unroll
    for (int i = 0; i < MT; i++)
        #pragma unroll
        for (int j = 0; j < NT; j++)
            #pragma unroll
            for (int e = 0; e < 4; e++) acc[i][j][e] = 0.f;

    for (int k0 = 0; k0 < K; k0 += BK) {
        // ---- fill A tile: 128x16 floats, 8 per thread (2 float4) ----
        {
            int idx = tid * 8;
            int row = idx >> 4;
            int col = idx & 15;
            const float* ap = A + (size_t)(brow + row)*K + k0 + col;
            float4 v0 = *(const float4*)ap;
            float4 v1 = *(const float4*)(ap + 4);
            float vv[8] = {v0.x, v0.y, v0.z, v0.w, v1.x, v1.y, v1.z, v1.w};
            #pragma unroll
            for (int j = 0; j < 8; j++) {
                uint32_t h, l; tf32_split(vv[j], h, l);
                As[0][row][col + j] = h;
                As[1][row][col + j] = l;
            }
        }
        // ---- fill B tile: 16xBN floats ----
        #pragma unroll
        for (int e = tid; e < BK*BN; e += 256) {
            int kk = e / BN, c = e % BN;
            float v = B[(size_t)(k0 + kk)*N + bcol + c];
            uint32_t h, l; tf32_split(v, h, l);
            Bs[0][kk][c] = h;
            Bs[1][kk][c] = l;
        }
        __syncthreads();

        #pragma unroll
        for (int ks = 0; ks < BK/8; ks++) {
            uint32_t bh[NT][2], bl[NT][2];
            #pragma unroll
            for (int nt = 0; nt < NT; nt++) {
                int bc = wn0 + nt*8 + lr;
                bh[nt][0] = Bs[0][ks*8 + lc    ][bc];
                bh[nt][1] = Bs[0][ks*8 + 4 + lc][bc];
                bl[nt][0] = Bs[1][ks*8 + lc    ][bc];
                bl[nt][1] = Bs[1][ks*8 + 4 + lc][bc];
            }
            #pragma unroll
            for (int mt = 0; mt < MT; mt++) {
                int r0 = wm0 + mt*16 + lr;
                uint32_t ah0 = As[0][r0    ][ks*8 + lc];
                uint32_t ah1 = As[0][r0 + 8][ks*8 + lc];
                uint32_t ah2 = As[0][r0    ][ks*8 + 4 + lc];
                uint32_t ah3 = As[0][r0 + 8][ks*8 + 4 + lc];
                uint32_t al0 = As[1][r0    ][ks*8 + lc];
                uint32_t al1 = As[1][r0 + 8][ks*8 + lc];
                uint32_t al2 = As[1][r0    ][ks*8 + 4 + lc];
                uint32_t al3 = As[1][r0 + 8][ks*8 + 4 + lc];
                #pragma unroll
                for (int nt = 0; nt < NT; nt++) {
                    mma_tf32(acc[mt][nt], ah0, ah1, ah2, ah3, bh[nt][0], bh[nt][1]);
                    mma_tf32(acc[mt][nt], al0, al1, al2, al3, bh[nt][0], bh[nt][1]);
                    mma_tf32(acc[mt][nt], ah0, ah1, ah2, ah3, bl[nt][0], bl[nt][1]);
                }
            }
        }
        __syncthreads();
    }

    // ---- epilogue ----
    #pragma unroll
    for (int mt = 0; mt < MT; mt++) {
        int r = brow + wm0 + mt*16 + lr;
        #pragma unroll
        for (int nt = 0; nt < NT; nt++) {
            int c = bcol + wn0 + nt*8 + lc*2;
            *(float2*)(C + (size_t)r*N + c)       = make_float2(acc[mt][nt][0], acc[mt][nt][1]);
            *(float2*)(C + (size_t)(r + 8)*N + c) = make_float2(acc[mt][nt][2], acc[mt][nt][3]);
        }
    }
}

// ---------------- K2: expm of 4x4 skew-symmetric ----------------
__device__ __forceinline__ void mm4(const float* __restrict__ A,
                                    const float* __restrict__ B,
                                    float* __restrict__ C) {
    #pragma unroll
    for (int i = 0; i < 4; i++)
        #pragma unroll
        for (int j = 0; j < 4; j++)
            C[i*4+j] = A[i*4+0]*B[0*4+j] + A[i*4+1]*B[1*4+j]
                     + A[i*4+2]*B[2*4+j] + A[i*4+3]*B[3*4+j];
}

__global__ void expm_kernel() {
    int tid = blockIdx.x*blockDim.x + threadIdx.x;   // chain-major: chain*Tt + t
    if (tid >= CHAINS*Tt) return;
    int t     = tid & (Tt-1);
    int chain = tid >> 12;
    int b     = chain >> 4;
    int h     = chain & 15;
    int n     = b*Tt + t;

    const float* s = g_SV + (size_t)n*NCOLS1 + h*NSKEW;
    float a01 = s[0], a02 = s[1], a03 = s[2], a12 = s[3], a13 = s[4], a23 = s[5];

    float fr = sqrtf(2.0f*(a01*a01 + a02*a02 + a03*a03 +
                           a12*a12 + a13*a13 + a23*a23));
    int sft = 0;
    float f = fr;
    while (f > 0.25f && sft < 32) { f *= 0.5f; sft++; }
    float sc = ldexpf(1.0f, -sft);

    float A[16] = {  0.f,  a01,  a02,  a03,
                    -a01,  0.f,  a12,  a13,
                    -a02, -a12,  0.f,  a23,
                    -a03, -a13, -a23,  0.f };
    #pragma unroll
    for (int e = 0; e < 16; e++) A[e] *= sc;

    float Tm[16], Tmp[16];
    #pragma unroll
    for (int e = 0; e < 16; e++)
        Tm[e] = A[e]*(1.0f/8.0f) + ((e % 5 == 0) ? 1.0f : 0.0f);
    #pragma unroll
    for (int k = 7; k >= 1; k--) {
        mm4(A, Tm, Tmp);
        float inv = 1.0f/(float)k;
        #pragma unroll
        for (int e = 0; e < 16; e++)
            Tm[e] = Tmp[e]*inv + ((e % 5 == 0) ? 1.0f : 0.0f);
    }
    for (int q = 0; q < sft; q++) {
        mm4(Tm, Tm, Tmp);
        #pragma unroll
        for (int e = 0; e < 16; e++) Tm[e] = Tmp[e];
    }

    float4* out = (float4*)(g_R + (size_t)tid*16);
    out[0] = make_float4(Tm[0],  Tm[1],  Tm[2],  Tm[3]);
    out[1] = make_float4(Tm[4],  Tm[5],  Tm[6],  Tm[7]);
    out[2] = make_float4(Tm[8],  Tm[9],  Tm[10], Tm[11]);
    out[3] = make_float4(Tm[12], Tm[13], Tm[14], Tm[15]);
}

// ---------------- K3: chunk-local prefix products ----------------
__global__ void scan_local_kernel() {
    int gtid  = blockIdx.x*blockDim.x + threadIdx.x;
    int lane  = gtid & 3;
    int g     = gtid >> 2;
    if (g >= CHAINS*NCHUNK) return;
    int chunk = g & (NCHUNK-1);
    int chain = g >> 7;                    // NCHUNK == 128

    const float4* Rb = (const float4*)(g_R + ((size_t)chain*Tt + chunk*CHUNK)*16);
    float* Lb        = g_L + ((size_t)chain*Tt + chunk*CHUNK)*16;

    float m0 = (lane==0), m1 = (lane==1), m2 = (lane==2), m3 = (lane==3);
    #pragma unroll 4
    for (int t = 0; t < CHUNK; t++) {
        float4 r0 = Rb[t*4+0], r1 = Rb[t*4+1], r2 = Rb[t*4+2], r3 = Rb[t*4+3];
        float n0 = r0.x*m0 + r0.y*m1 + r0.z*m2 + r0.w*m3;
        float n1 = r1.x*m0 + r1.y*m1 + r1.z*m2 + r1.w*m3;
        float n2 = r2.x*m0 + r2.y*m1 + r2.z*m2 + r2.w*m3;
        float n3 = r3.x*m0 + r3.y*m1 + r3.z*m2 + r3.w*m3;
        m0 = n0; m1 = n1; m2 = n2; m3 = n3;
        Lb[t*16 +  0 + lane] = m0;
        Lb[t*16 +  4 + lane] = m1;
        Lb[t*16 +  8 + lane] = m2;
        Lb[t*16 + 12 + lane] = m3;
    }
    float* Cb = g_Ctot + ((size_t)chain*NCHUNK + chunk)*16;
    Cb[ 0 + lane] = m0; Cb[ 4 + lane] = m1;
    Cb[ 8 + lane] = m2; Cb[12 + lane] = m3;
}

// ---------------- K4: exclusive prefix over chunk totals ----------------
__global__ void prefix_kernel() {
    int tid = threadIdx.x;
    if (tid >= CHAINS*4) return;
    int lane  = tid & 3;
    int chain = tid >> 2;

    const float4* Cb = (const float4*)(g_Ctot + (size_t)chain*NCHUNK*16);
    float p0 = (lane==0), p1 = (lane==1), p2 = (lane==2), p3 = (lane==3);

    float4 r0 = Cb[0], r1 = Cb[1], r2 = Cb[2], r3 = Cb[3];
    for (int c = 0; c < NCHUNK; c++) {
        float4 n0, n1, n2, n3;
        bool more = (c + 1 < NCHUNK);
        if (more) {
            const float4* Nb = Cb + (size_t)(c+1)*4;
            n0 = Nb[0]; n1 = Nb[1]; n2 = Nb[2]; n3 = Nb[3];
        }
        float* Pb = g_Pprev + ((size_t)chain*NCHUNK + c)*16;
        Pb[ 0 + lane] = p0; Pb[ 4 + lane] = p1;
        Pb[ 8 + lane] = p2; Pb[12 + lane] = p3;

        float q0 = r0.x*p0 + r0.y*p1 + r0.z*p2 + r0.w*p3;
        float q1 = r1.x*p0 + r1.y*p1 + r1.z*p2 + r1.w*p3;
        float q2 = r2.x*p0 + r2.y*p1 + r2.z*p2 + r2.w*p3;
        float q3 = r3.x*p0 + r3.y*p1 + r3.z*p2 + r3.w*p3;
        p0 = q0; p1 = q1; p2 = q2; p3 = q3;
        if (more) { r0 = n0; r1 = n1; r2 = n2; r3 = n3; }
    }
}

// ---------------- K5: rotated[t] = local[t] @ (P_prev @ v[t]) ----------------
__global__ void rotate_kernel() {
    int tid = blockIdx.x*blockDim.x + threadIdx.x;
    if (tid >= CHAINS*Tt) return;
    int t     = tid & (Tt-1);
    int chain = tid >> 12;
    int b     = chain >> 4;
    int h     = chain & 15;
    int n     = b*Tt + t;
    int chunk = t / CHUNK;

    float4 v = *(const float4*)(g_SV + (size_t)n*NCOLS1 + VOFF + h*Nn);
    const float* P = g_Pprev + ((size_t)chain*NCHUNK + chunk)*16;
    float u0 = P[ 0]*v.x + P[ 1]*v.y + P[ 2]*v.z + P[ 3]*v.w;
    float u1 = P[ 4]*v.x + P[ 5]*v.y + P[ 6]*v.z + P[ 7]*v.w;
    float u2 = P[ 8]*v.x + P[ 9]*v.y + P[10]*v.z + P[11]*v.w;
    float u3 = P[12]*v.x + P[13]*v.y + P[14]*v.z + P[15]*v.w;

    const float4* L = (const float4*)(g_L + (size_t)tid*16);
    float4 l0 = L[0], l1 = L[1], l2 = L[2], l3 = L[3];
    float r0 = l0.x*u0 + l0.y*u1 + l0.z*u2 + l0.w*u3;
    float r1 = l1.x*u0 + l1.y*u1 + l1.z*u2 + l1.w*u3;
    float r2 = l2.x*u0 + l2.y*u1 + l2.z*u2 + l2.w*u3;
    float r3 = l3.x*u0 + l3.y*u1 + l3.z*u2 + l3.w*u3;

    *(float4*)(g_Rot + (size_t)n*HN + h*Nn) = make_float4(r0, r1, r2, r3);
}

// ---------------- launcher ----------------
extern "C" void kernel_launch(void* const* d_in, const int* in_sizes, int n_in,
                              void* d_out, int out_size) {
    const float* x     = (const float*)d_in[0];
    const float* Wskew = (const float*)d_in[1];
    const float* Wv    = (const float*)d_in[2];
    const float* Wo    = (const float*)d_in[3];
    float* out = (float*)d_out;

    float* g_Wcat_p;  cudaGetSymbolAddress((void**)&g_Wcat_p, g_Wcat);
    float* g_SV_p;    cudaGetSymbolAddress((void**)&g_SV_p,   g_SV);
    float* g_Rot_p;   cudaGetSymbolAddress((void**)&g_Rot_p,  g_Rot);

    concat_w_kernel<<<(D_MODEL*NCOLS1 + 255)/256, 256>>>(Wskew, Wv);
    gemm_tf32_kernel<NCOLS1, D_MODEL, 32><<<dim3(NCOLS1/32, NROWS/128), 256>>>(x, g_Wcat_p, g_SV_p);
    expm_kernel<<<(CHAINS*Tt)/256, 256>>>();
    scan_local_kernel<<<(CHAINS*NCHUNK*4)/256, 256>>>();
    prefix_kernel<<<1, 256>>>();
    rotate_kernel<<<(CHAINS*Tt)/256, 256>>>();
    gemm_tf32_kernel<D_MODEL, HN, 64><<<dim3(D_MODEL/64, NROWS/128), 256>>>(g_Rot_p, Wo, out);
}

// round 4
// speedup vs baseline: 2.5287x; 2.5287x over previous
#include <cuda_runtime.h>
#include <cuda_bf16.h>
#include <cstdint>

// ---------------- problem constants ----------------
#define D_MODEL 1024
#define Hh      16
#define Nn      4
#define NSKEW   6
#define Bb      4
#define Tt      4096
#define NROWS   (Bb*Tt)                    // 16384
#define NCOLS1  (Hh*NSKEW + Hh*Nn)         // 160
#define VOFF    (Hh*NSKEW)                 // 96
#define HN      (Hh*Nn)                    // 64
#define CHAINS  (Bb*Hh)                    // 64
#define CHUNK   16
#define NCHUNK  (Tt/CHUNK)                 // 256

// ---------------- scratch ----------------
__device__ float g_Bt1 [NCOLS1*D_MODEL];        // Wcat^T  (160 x 1024)
__device__ float g_Bt2 [D_MODEL*HN];            // Wo^T    (1024 x 64)
__device__ float g_SV  [NROWS*NCOLS1];
__device__ float g_R   [CHAINS*Tt*16];
__device__ float g_L   [CHAINS*Tt*16];
__device__ float g_Ctot[CHAINS*NCHUNK*16];
__device__ float g_Pprev[CHAINS*NCHUNK*16];
__device__ float g_Rot [NROWS*HN];

// ---------------- bf16 helpers ----------------
__device__ __forceinline__ void mma_bf16(float* c,
                                         uint32_t a0, uint32_t a1, uint32_t a2, uint32_t a3,
                                         uint32_t b0, uint32_t b1) {
    asm volatile(
        "mma.sync.aligned.m16n8k16.row.col.f32.bf16.bf16.f32 "
        "{%0,%1,%2,%3}, {%4,%5,%6,%7}, {%8,%9}, {%0,%1,%2,%3};"
        : "+f"(c[0]), "+f"(c[1]), "+f"(c[2]), "+f"(c[3])
        : "r"(a0), "r"(a1), "r"(a2), "r"(a3), "r"(b0), "r"(b1));
}

__device__ __forceinline__ void split_pack(float4 v, uint2& hi, uint2& lo) {
    __nv_bfloat16 hx = __float2bfloat16_rn(v.x);
    __nv_bfloat16 hy = __float2bfloat16_rn(v.y);
    __nv_bfloat16 hz = __float2bfloat16_rn(v.z);
    __nv_bfloat16 hw = __float2bfloat16_rn(v.w);
    __nv_bfloat16 lx = __float2bfloat16_rn(v.x - __bfloat162float(hx));
    __nv_bfloat16 ly = __float2bfloat16_rn(v.y - __bfloat162float(hy));
    __nv_bfloat16 lz = __float2bfloat16_rn(v.z - __bfloat162float(hz));
    __nv_bfloat16 lw = __float2bfloat16_rn(v.w - __bfloat162float(hw));
    hi.x = (uint32_t)__bfloat16_as_ushort(hx) | ((uint32_t)__bfloat16_as_ushort(hy) << 16);
    hi.y = (uint32_t)__bfloat16_as_ushort(hz) | ((uint32_t)__bfloat16_as_ushort(hw) << 16);
    lo.x = (uint32_t)__bfloat16_as_ushort(lx) | ((uint32_t)__bfloat16_as_ushort(ly) << 16);
    lo.y = (uint32_t)__bfloat16_as_ushort(lz) | ((uint32_t)__bfloat16_as_ushort(lw) << 16);
}

// ---------------- bf16-split HMMA GEMM ----------------
// C[M,NTOT] = A[M,KTOT] @ Bt[NTOT,KTOT]^T  (fp32 row-major everywhere).
// BM=128 rows per CTA, BN cols per CTA (grid.x tiles of BN), K stepped by 16.
// 8 warps in 4(m) x 2(n) raster; warp tile 32 x (BN/2); MT=2, NT=BN/16.
template<int BN, int NTOT, int KTOT>
__global__ void __launch_bounds__(256) gemm_bf16_kernel(const float* __restrict__ A,
                                                        const float* __restrict__ Bt,
                                                        float* __restrict__ C) {
    constexpr int BM = 128, KC = 16;
    constexpr int NSTEP = KTOT / KC;
    constexpr int WARPS_M = 4, WARPS_N = 2;
    constexpr int WM = BM / WARPS_M;        // 32
    constexpr int WN = BN / WARPS_N;        // 80 or 64
    constexpr int MT = WM / 16;             // 2
    constexpr int NT = WN / 8;              // 10 or 8
    constexpr int RS = 48;                  // smem row stride bytes (32B data + 16B pad)
    constexpr int NF4 = (BM + BN) * 4;      // float4s per k-chunk
    constexpr int MAXR = (NF4 + 255) / 256;

    __shared__ __align__(16) unsigned char smem[(2*BM + 2*BN) * RS];
    constexpr int AHI = 0;
    constexpr int ALO = BM * RS;
    constexpr int BHI = 2 * BM * RS;
    constexpr int BLO = 2 * BM * RS + BN * RS;

    const int tid  = threadIdx.x;
    const int warp = tid >> 5;
    const int lane = tid & 31;
    const int brow = blockIdx.y * BM;
    const int bcol = blockIdx.x * BN;
    const int wm0  = (warp >> 1) * WM;      // warp/WARPS_N * WM
    const int wn0  = (warp & 1) * WN;
    const int gr   = lane >> 2;             // 0..7
    const int lc   = lane & 3;              // 0..3

    float acc[MT][NT][4];
    #pragma unroll
    for (int i = 0; i < MT; i++)
        #pragma unroll
        for (int j = 0; j < NT; j++)
            #pragma unroll
            for (int e = 0; e < 4; e++) acc[i][j][e] = 0.f;

    // prologue: prefetch k-chunk 0 into registers
    float4 pf[MAXR];
    #pragma unroll
    for (int r = 0; r < MAXR; r++) {
        int e = tid + r*256;
        if (e < NF4) {
            if (e < BM*4) {
                int row = e >> 2, q = e & 3;
                pf[r] = *(const float4*)(A + (size_t)(brow + row)*KTOT + q*4);
            } else {
                int e2 = e - BM*4, row = e2 >> 2, q = e2 & 3;
                pf[r] = *(const float4*)(Bt + (size_t)(bcol + row)*KTOT + q*4);
            }
        }
    }

    for (int s = 0; s < NSTEP; s++) {
        __syncthreads();                    // previous compute done with smem
        // store prefetched chunk (convert to bf16 hi/lo)
        #pragma unroll
        for (int r = 0; r < MAXR; r++) {
            int e = tid + r*256;
            if (e < NF4) {
                uint2 hi, lo;
                split_pack(pf[r], hi, lo);
                int dh, dl, row, q;
                if (e < BM*4) { row = e >> 2; q = e & 3; dh = AHI; dl = ALO; }
                else { int e2 = e - BM*4; row = e2 >> 2; q = e2 & 3; dh = BHI; dl = BLO; }
                *(uint2*)&smem[dh + row*RS + q*8] = hi;
                *(uint2*)&smem[dl + row*RS + q*8] = lo;
            }
        }
        __syncthreads();
        // prefetch next chunk
        if (s + 1 < NSTEP) {
            #pragma unroll
            for (int r = 0; r < MAXR; r++) {
                int e = tid + r*256;
                if (e < NF4) {
                    if (e < BM*4) {
                        int row = e >> 2, q = e & 3;
                        pf[r] = *(const float4*)(A + (size_t)(brow + row)*KTOT + (s+1)*KC + q*4);
                    } else {
                        int e2 = e - BM*4, row = e2 >> 2, q = e2 & 3;
                        pf[r] = *(const float4*)(Bt + (size_t)(bcol + row)*KTOT + (s+1)*KC + q*4);
                    }
                }
            }
        }
        // ---- compute on smem tiles ----
        uint32_t ah[MT][4], al[MT][4];
        #pragma unroll
        for (int mt = 0; mt < MT; mt++) {
            int ro = (wm0 + mt*16 + gr) * RS + lc*4;
            ah[mt][0] = *(const uint32_t*)&smem[AHI + ro];
            ah[mt][1] = *(const uint32_t*)&smem[AHI + ro + 8*RS];
            ah[mt][2] = *(const uint32_t*)&smem[AHI + ro + 16];
            ah[mt][3] = *(const uint32_t*)&smem[AHI + ro + 8*RS + 16];
            al[mt][0] = *(const uint32_t*)&smem[ALO + ro];
            al[mt][1] = *(const uint32_t*)&smem[ALO + ro + 8*RS];
            al[mt][2] = *(const uint32_t*)&smem[ALO + ro + 16];
            al[mt][3] = *(const uint32_t*)&smem[ALO + ro + 8*RS + 16];
        }
        #pragma unroll
        for (int nt = 0; nt < NT; nt++) {
            int ro = (wn0 + nt*8 + gr) * RS + lc*4;
            uint32_t bh0 = *(const uint32_t*)&smem[BHI + ro];
            uint32_t bh1 = *(const uint32_t*)&smem[BHI + ro + 16];
            uint32_t bl0 = *(const uint32_t*)&smem[BLO + ro];
            uint32_t bl1 = *(const uint32_t*)&smem[BLO + ro + 16];
            #pragma unroll
            for (int mt = 0; mt < MT; mt++) {
                mma_bf16(acc[mt][nt], ah[mt][0], ah[mt][1], ah[mt][2], ah[mt][3], bh0, bh1);
                mma_bf16(acc[mt][nt], al[mt][0], al[mt][1], al[mt][2], al[mt][3], bh0, bh1);
                mma_bf16(acc[mt][nt], ah[mt][0], ah[mt][1], ah[mt][2], ah[mt][3], bl0, bl1);
            }
        }
    }

    // ---- epilogue ----
    #pragma unroll
    for (int mt = 0; mt < MT; mt++) {
        int r0 = brow + wm0 + mt*16 + gr;
        #pragma unroll
        for (int nt = 0; nt < NT; nt++) {
            int c0 = bcol + wn0 + nt*8 + 2*lc;
            *(float2*)(C + (size_t)r0*NTOT + c0)       = make_float2(acc[mt][nt][0], acc[mt][nt][1]);
            *(float2*)(C + (size_t)(r0 + 8)*NTOT + c0) = make_float2(acc[mt][nt][2], acc[mt][nt][3]);
        }
    }
}

// ---------------- K0: transpose/concat weights ----------------
__global__ void prep_kernel(const float* __restrict__ Wskew,
                            const float* __restrict__ Wv,
                            const float* __restrict__ Wo) {
    int i = blockIdx.x*blockDim.x + threadIdx.x;
    if (i < NCOLS1*D_MODEL) {
        int n = i >> 10, k = i & 1023;           // g_Bt1[n][k] = Wcat[k][n]
        g_Bt1[i] = (n < VOFF) ? Wskew[k*VOFF + n] : Wv[k*HN + (n - VOFF)];
    } else {
        int j = i - NCOLS1*D_MODEL;
        if (j < D_MODEL*HN) {
            int n = j >> 6, k = j & 63;          // g_Bt2[n][k] = Wo[k][n]
            g_Bt2[j] = Wo[k*D_MODEL + n];
        }
    }
}

// ---------------- K2: expm of 4x4 skew-symmetric ----------------
__device__ __forceinline__ void mm4(const float* __restrict__ A,
                                    const float* __restrict__ B,
                                    float* __restrict__ C) {
    #pragma unroll
    for (int i = 0; i < 4; i++)
        #pragma unroll
        for (int j = 0; j < 4; j++)
            C[i*4+j] = A[i*4+0]*B[0*4+j] + A[i*4+1]*B[1*4+j]
                     + A[i*4+2]*B[2*4+j] + A[i*4+3]*B[3*4+j];
}

__global__ void expm_kernel() {
    int tid = blockIdx.x*blockDim.x + threadIdx.x;   // chain-major: chain*Tt + t
    if (tid >= CHAINS*Tt) return;
    int t     = tid & (Tt-1);
    int chain = tid >> 12;
    int b     = chain >> 4;
    int h     = chain & 15;
    int n     = b*Tt + t;

    const float* s = g_SV + (size_t)n*NCOLS1 + h*NSKEW;
    float a01 = s[0], a02 = s[1], a03 = s[2], a12 = s[3], a13 = s[4], a23 = s[5];

    float fr = sqrtf(2.0f*(a01*a01 + a02*a02 + a03*a03 +
                           a12*a12 + a13*a13 + a23*a23));
    int sft = 0;
    float f = fr;
    while (f > 0.25f && sft < 32) { f *= 0.5f; sft++; }
    float sc = ldexpf(1.0f, -sft);

    float A[16] = {  0.f,  a01,  a02,  a03,
                    -a01,  0.f,  a12,  a13,
                    -a02, -a12,  0.f,  a23,
                    -a03, -a13, -a23,  0.f };
    #pragma unroll
    for (int e = 0; e < 16; e++) A[e] *= sc;

    float Tm[16], Tmp[16];
    #pragma unroll
    for (int e = 0; e < 16; e++)
        Tm[e] = A[e]*(1.0f/8.0f) + ((e % 5 == 0) ? 1.0f : 0.0f);
    #pragma unroll
    for (int k = 7; k >= 1; k--) {
        mm4(A, Tm, Tmp);
        float inv = 1.0f/(float)k;
        #pragma unroll
        for (int e = 0; e < 16; e++)
            Tm[e] = Tmp[e]*inv + ((e % 5 == 0) ? 1.0f : 0.0f);
    }
    for (int q = 0; q < sft; q++) {
        mm4(Tm, Tm, Tmp);
        #pragma unroll
        for (int e = 0; e < 16; e++) Tm[e] = Tmp[e];
    }

    float4* out = (float4*)(g_R + (size_t)tid*16);
    out[0] = make_float4(Tm[0],  Tm[1],  Tm[2],  Tm[3]);
    out[1] = make_float4(Tm[4],  Tm[5],  Tm[6],  Tm[7]);
    out[2] = make_float4(Tm[8],  Tm[9],  Tm[10], Tm[11]);
    out[3] = make_float4(Tm[12], Tm[13], Tm[14], Tm[15]);
}

// ---------------- K3: chunk-local prefix products ----------------
// 4 threads per (chain, chunk); thread `lane` owns column `lane`.
__global__ void scan_local_kernel() {
    int gtid  = blockIdx.x*blockDim.x + threadIdx.x;
    int lane  = gtid & 3;
    int g     = gtid >> 2;
    if (g >= CHAINS*NCHUNK) return;
    int chunk = g & (NCHUNK-1);
    int chain = g >> 8;                    // NCHUNK == 256

    const float4* Rb = (const float4*)(g_R + ((size_t)chain*Tt + chunk*CHUNK)*16);
    float* Lb        = g_L + ((size_t)chain*Tt + chunk*CHUNK)*16;

    float m0 = (lane==0), m1 = (lane==1), m2 = (lane==2), m3 = (lane==3);
    #pragma unroll 4
    for (int t = 0; t < CHUNK; t++) {
        float4 r0 = Rb[t*4+0], r1 = Rb[t*4+1], r2 = Rb[t*4+2], r3 = Rb[t*4+3];
        float n0 = r0.x*m0 + r0.y*m1 + r0.z*m2 + r0.w*m3;
        float n1 = r1.x*m0 + r1.y*m1 + r1.z*m2 + r1.w*m3;
        float n2 = r2.x*m0 + r2.y*m1 + r2.z*m2 + r2.w*m3;
        float n3 = r3.x*m0 + r3.y*m1 + r3.z*m2 + r3.w*m3;
        m0 = n0; m1 = n1; m2 = n2; m3 = n3;
        Lb[t*16 +  0 + lane] = m0;
        Lb[t*16 +  4 + lane] = m1;
        Lb[t*16 +  8 + lane] = m2;
        Lb[t*16 + 12 + lane] = m3;
    }
    float* Cb = g_Ctot + ((size_t)chain*NCHUNK + chunk)*16;
    Cb[ 0 + lane] = m0; Cb[ 4 + lane] = m1;
    Cb[ 8 + lane] = m2; Cb[12 + lane] = m3;
}

// ---------------- K4: Kogge-Stone scan over chunk totals (per chain) ----------------
// 64 blocks (one per chain) x 256 threads (one per chunk).
__global__ void __launch_bounds__(NCHUNK) prefix_kernel() {
    __shared__ float sm[NCHUNK*17];
    const int i     = threadIdx.x;
    const int chain = blockIdx.x;

    float M[16];
    const float* Cb = g_Ctot + ((size_t)chain*NCHUNK + i)*16;
    #pragma unroll
    for (int e = 0; e < 16; e++) M[e] = Cb[e];

    #pragma unroll
    for (int d = 1; d < NCHUNK; d <<= 1) {
        #pragma unroll
        for (int e = 0; e < 16; e++) sm[i*17 + e] = M[e];
        __syncthreads();
        if (i >= d) {
            float P[16], T[16];
            #pragma unroll
            for (int e = 0; e < 16; e++) P[e] = sm[(i-d)*17 + e];
            mm4(M, P, T);                       // newer (M) on the left
            #pragma unroll
            for (int e = 0; e < 16; e++) M[e] = T[e];
        }
        __syncthreads();
    }

    // exclusive shift: P_prev[i] = inclusive[i-1], P_prev[0] = I
    #pragma unroll
    for (int e = 0; e < 16; e++) sm[i*17 + e] = M[e];
    __syncthreads();
    float* Pb = g_Pprev + ((size_t)chain*NCHUNK + i)*16;
    if (i == 0) {
        #pragma unroll
        for (int e = 0; e < 16; e++) Pb[e] = (e % 5 == 0) ? 1.0f : 0.0f;
    } else {
        #pragma unroll
        for (int e = 0; e < 16; e++) Pb[e] = sm[(i-1)*17 + e];
    }
}

// ---------------- K5: rotated[t] = local[t] @ (P_prev @ v[t]) ----------------
__global__ void rotate_kernel() {
    int tid = blockIdx.x*blockDim.x + threadIdx.x;
    if (tid >= CHAINS*Tt) return;
    int t     = tid & (Tt-1);
    int chain = tid >> 12;
    int b     = chain >> 4;
    int h     = chain & 15;
    int n     = b*Tt + t;
    int chunk = t >> 4;                    // CHUNK == 16

    float4 v = *(const float4*)(g_SV + (size_t)n*NCOLS1 + VOFF + h*Nn);
    const float* P = g_Pprev + ((size_t)chain*NCHUNK + chunk)*16;
    float u0 = P[ 0]*v.x + P[ 1]*v.y + P[ 2]*v.z + P[ 3]*v.w;
    float u1 = P[ 4]*v.x + P[ 5]*v.y + P[ 6]*v.z + P[ 7]*v.w;
    float u2 = P[ 8]*v.x + P[ 9]*v.y + P[10]*v.z + P[11]*v.w;
    float u3 = P[12]*v.x + P[13]*v.y + P[14]*v.z + P[15]*v.w;

    const float4* L = (const float4*)(g_L + (size_t)tid*16);
    float4 l0 = L[0], l1 = L[1], l2 = L[2], l3 = L[3];
    float r0 = l0.x*u0 + l0.y*u1 + l0.z*u2 + l0.w*u3;
    float r1 = l1.x*u0 + l1.y*u1 + l1.z*u2 + l1.w*u3;
    float r2 = l2.x*u0 + l2.y*u1 + l2.z*u2 + l2.w*u3;
    float r3 = l3.x*u0 + l3.y*u1 + l3.z*u2 + l3.w*u3;

    *(float4*)(g_Rot + (size_t)n*HN + h*Nn) = make_float4(r0, r1, r2, r3);
}

// ---------------- launcher ----------------
extern "C" void kernel_launch(void* const* d_in, const int* in_sizes, int n_in,
                              void* d_out, int out_size) {
    const float* x     = (const float*)d_in[0];
    const float* Wskew = (const float*)d_in[1];
    const float* Wv    = (const float*)d_in[2];
    const float* Wo    = (const float*)d_in[3];
    float* out = (float*)d_out;

    float *g_Bt1_p, *g_Bt2_p, *g_SV_p, *g_Rot_p;
    cudaGetSymbolAddress((void**)&g_Bt1_p, g_Bt1);
    cudaGetSymbolAddress((void**)&g_Bt2_p, g_Bt2);
    cudaGetSymbolAddress((void**)&g_SV_p,  g_SV);
    cudaGetSymbolAddress((void**)&g_Rot_p, g_Rot);

    prep_kernel<<<(NCOLS1*D_MODEL + D_MODEL*HN + 255)/256, 256>>>(Wskew, Wv, Wo);
    gemm_bf16_kernel<NCOLS1, NCOLS1, D_MODEL>
        <<<dim3(1, NROWS/128), 256>>>(x, g_Bt1_p, g_SV_p);
    expm_kernel<<<(CHAINS*Tt)/256, 256>>>();
    scan_local_kernel<<<(CHAINS*NCHUNK*4)/256, 256>>>();
    prefix_kernel<<<CHAINS, NCHUNK>>>();
    rotate_kernel<<<(CHAINS*Tt)/256, 256>>>();
    gemm_bf16_kernel<128, D_MODEL, HN>
        <<<dim3(D_MODEL/128, NROWS/128), 256>>>(g_Rot_p, g_Bt2_p, out);
}

// round 5
// speedup vs baseline: 2.5865x; 1.0229x over previous
#include <cuda_runtime.h>
#include <cuda_bf16.h>
#include <cstdint>

// ---------------- problem constants ----------------
#define D_MODEL 1024
#define Hh      16
#define Nn      4
#define NSKEW   6
#define Bb      4
#define Tt      4096
#define NROWS   (Bb*Tt)                    // 16384
#define NCOLS1  (Hh*NSKEW + Hh*Nn)         // 160
#define VOFF    (Hh*NSKEW)                 // 96
#define HN      (Hh*Nn)                    // 64
#define CHAINS  (Bb*Hh)                    // 64
#define CHUNK   16
#define NCHUNK  (Tt/CHUNK)                 // 256

// ---------------- scratch ----------------
__device__ float g_Bt1 [NCOLS1*D_MODEL];        // Wcat^T  (160 x 1024)
__device__ float g_Bt2 [D_MODEL*HN];            // Wo^T    (1024 x 64)
__device__ float g_SV  [NROWS*NCOLS1];
__device__ float g_R   [CHAINS*Tt*16];
__device__ float g_L   [CHAINS*Tt*16];
__device__ float g_Ctot[CHAINS*NCHUNK*16];
__device__ float g_Pprev[CHAINS*NCHUNK*16];
__device__ float g_Rot [NROWS*HN];

// ---------------- bf16 helpers ----------------
__device__ __forceinline__ void mma_bf16(float* c,
                                         uint32_t a0, uint32_t a1, uint32_t a2, uint32_t a3,
                                         uint32_t b0, uint32_t b1) {
    asm volatile(
        "mma.sync.aligned.m16n8k16.row.col.f32.bf16.bf16.f32 "
        "{%0,%1,%2,%3}, {%4,%5,%6,%7}, {%8,%9}, {%0,%1,%2,%3};"
        : "+f"(c[0]), "+f"(c[1]), "+f"(c[2]), "+f"(c[3])
        : "r"(a0), "r"(a1), "r"(a2), "r"(a3), "r"(b0), "r"(b1));
}

__device__ __forceinline__ void split_pack(float4 v, uint2& hi, uint2& lo) {
    __nv_bfloat16 hx = __float2bfloat16_rn(v.x);
    __nv_bfloat16 hy = __float2bfloat16_rn(v.y);
    __nv_bfloat16 hz = __float2bfloat16_rn(v.z);
    __nv_bfloat16 hw = __float2bfloat16_rn(v.w);
    __nv_bfloat16 lx = __float2bfloat16_rn(v.x - __bfloat162float(hx));
    __nv_bfloat16 ly = __float2bfloat16_rn(v.y - __bfloat162float(hy));
    __nv_bfloat16 lz = __float2bfloat16_rn(v.z - __bfloat162float(hz));
    __nv_bfloat16 lw = __float2bfloat16_rn(v.w - __bfloat162float(hw));
    hi.x = (uint32_t)__bfloat16_as_ushort(hx) | ((uint32_t)__bfloat16_as_ushort(hy) << 16);
    hi.y = (uint32_t)__bfloat16_as_ushort(hz) | ((uint32_t)__bfloat16_as_ushort(hw) << 16);
    lo.x = (uint32_t)__bfloat16_as_ushort(lx) | ((uint32_t)__bfloat16_as_ushort(ly) << 16);
    lo.y = (uint32_t)__bfloat16_as_ushort(lz) | ((uint32_t)__bfloat16_as_ushort(lw) << 16);
}

// ---------------- bf16-split HMMA GEMM ----------------
// C[M,NTOT] = A[M,KTOT] @ Bt[NTOT,KTOT]^T  (fp32 row-major everywhere).
// BM=128 rows per CTA, BN cols per CTA (grid.x tiles of BN), K stepped by 16.
// 8 warps in 4(m) x 2(n) raster; warp tile 32 x (BN/2); MT=2, NT=BN/16.
template<int BN, int NTOT, int KTOT>
__global__ void __launch_bounds__(256) gemm_bf16_kernel(const float* __restrict__ A,
                                                        const float* __restrict__ Bt,
                                                        float* __restrict__ C) {
    constexpr int BM = 128, KC = 16;
    constexpr int NSTEP = KTOT / KC;
    constexpr int WARPS_M = 4, WARPS_N = 2;
    constexpr int WM = BM / WARPS_M;        // 32
    constexpr int WN = BN / WARPS_N;        // 80 or 64
    constexpr int MT = WM / 16;             // 2
    constexpr int NT = WN / 8;              // 10 or 8
    constexpr int RS = 48;                  // smem row stride bytes (32B data + 16B pad)
    constexpr int NF4 = (BM + BN) * 4;      // float4s per k-chunk
    constexpr int MAXR = (NF4 + 255) / 256;

    __shared__ __align__(16) unsigned char smem[(2*BM + 2*BN) * RS];
    constexpr int AHI = 0;
    constexpr int ALO = BM * RS;
    constexpr int BHI = 2 * BM * RS;
    constexpr int BLO = 2 * BM * RS + BN * RS;

    const int tid  = threadIdx.x;
    const int warp = tid >> 5;
    const int lane = tid & 31;
    const int brow = blockIdx.y * BM;
    const int bcol = blockIdx.x * BN;
    const int wm0  = (warp >> 1) * WM;      // warp/WARPS_N * WM
    const int wn0  = (warp & 1) * WN;
    const int gr   = lane >> 2;             // 0..7
    const int lc   = lane & 3;              // 0..3

    float acc[MT][NT][4];
    #pragma unroll
    for (int i = 0; i < MT; i++)
        #pragma unroll
        for (int j = 0; j < NT; j++)
            #pragma unroll
            for (int e = 0; e < 4; e++) acc[i][j][e] = 0.f;

    // prologue: prefetch k-chunk 0 into registers
    float4 pf[MAXR];
    #pragma unroll
    for (int r = 0; r < MAXR; r++) {
        int e = tid + r*256;
        if (e < NF4) {
            if (e < BM*4) {
                int row = e >> 2, q = e & 3;
                pf[r] = *(const float4*)(A + (size_t)(brow + row)*KTOT + q*4);
            } else {
                int e2 = e - BM*4, row = e2 >> 2, q = e2 & 3;
                pf[r] = *(const float4*)(Bt + (size_t)(bcol + row)*KTOT + q*4);
            }
        }
    }

    for (int s = 0; s < NSTEP; s++) {
        __syncthreads();                    // previous compute done with smem
        // store prefetched chunk (convert to bf16 hi/lo)
        #pragma unroll
        for (int r = 0; r < MAXR; r++) {
            int e = tid + r*256;
            if (e < NF4) {
                uint2 hi, lo;
                split_pack(pf[r], hi, lo);
                int dh, dl, row, q;
                if (e < BM*4) { row = e >> 2; q = e & 3; dh = AHI; dl = ALO; }
                else { int e2 = e - BM*4; row = e2 >> 2; q = e2 & 3; dh = BHI; dl = BLO; }
                *(uint2*)&smem[dh + row*RS + q*8] = hi;
                *(uint2*)&smem[dl + row*RS + q*8] = lo;
            }
        }
        __syncthreads();
        // prefetch next chunk
        if (s + 1 < NSTEP) {
            #pragma unroll
            for (int r = 0; r < MAXR; r++) {
                int e = tid + r*256;
                if (e < NF4) {
                    if (e < BM*4) {
                        int row = e >> 2, q = e & 3;
                        pf[r] = *(const float4*)(A + (size_t)(brow + row)*KTOT + (s+1)*KC + q*4);
                    } else {
                        int e2 = e - BM*4, row = e2 >> 2, q = e2 & 3;
                        pf[r] = *(const float4*)(Bt + (size_t)(bcol + row)*KTOT + (s+1)*KC + q*4);
                    }
                }
            }
        }
        // ---- compute on smem tiles ----
        uint32_t ah[MT][4], al[MT][4];
        #pragma unroll
        for (int mt = 0; mt < MT; mt++) {
            int ro = (wm0 + mt*16 + gr) * RS + lc*4;
            ah[mt][0] = *(const uint32_t*)&smem[AHI + ro];
            ah[mt][1] = *(const uint32_t*)&smem[AHI + ro + 8*RS];
            ah[mt][2] = *(const uint32_t*)&smem[AHI + ro + 16];
            ah[mt][3] = *(const uint32_t*)&smem[AHI + ro + 8*RS + 16];
            al[mt][0] = *(const uint32_t*)&smem[ALO + ro];
            al[mt][1] = *(const uint32_t*)&smem[ALO + ro + 8*RS];
            al[mt][2] = *(const uint32_t*)&smem[ALO + ro + 16];
            al[mt][3] = *(const uint32_t*)&smem[ALO + ro + 8*RS + 16];
        }
        #pragma unroll
        for (int nt = 0; nt < NT; nt++) {
            int ro = (wn0 + nt*8 + gr) * RS + lc*4;
            uint32_t bh0 = *(const uint32_t*)&smem[BHI + ro];
            uint32_t bh1 = *(const uint32_t*)&smem[BHI + ro + 16];
            uint32_t bl0 = *(const uint32_t*)&smem[BLO + ro];
            uint32_t bl1 = *(const uint32_t*)&smem[BLO + ro + 16];
            #pragma unroll
            for (int mt = 0; mt < MT; mt++) {
                mma_bf16(acc[mt][nt], ah[mt][0], ah[mt][1], ah[mt][2], ah[mt][3], bh0, bh1);
                mma_bf16(acc[mt][nt], al[mt][0], al[mt][1], al[mt][2], al[mt][3], bh0, bh1);
                mma_bf16(acc[mt][nt], ah[mt][0], ah[mt][1], ah[mt][2], ah[mt][3], bl0, bl1);
            }
        }
    }

    // ---- epilogue ----
    #pragma unroll
    for (int mt = 0; mt < MT; mt++) {
        int r0 = brow + wm0 + mt*16 + gr;
        #pragma unroll
        for (int nt = 0; nt < NT; nt++) {
            int c0 = bcol + wn0 + nt*8 + 2*lc;
            *(float2*)(C + (size_t)r0*NTOT + c0)       = make_float2(acc[mt][nt][0], acc[mt][nt][1]);
            *(float2*)(C + (size_t)(r0 + 8)*NTOT + c0) = make_float2(acc[mt][nt][2], acc[mt][nt][3]);
        }
    }
}

// ---------------- K0: transpose/concat weights ----------------
__global__ void prep_kernel(const float* __restrict__ Wskew,
                            const float* __restrict__ Wv,
                            const float* __restrict__ Wo) {
    int i = blockIdx.x*blockDim.x + threadIdx.x;
    if (i < NCOLS1*D_MODEL) {
        int n = i >> 10, k = i & 1023;           // g_Bt1[n][k] = Wcat[k][n]
        g_Bt1[i] = (n < VOFF) ? Wskew[k*VOFF + n] : Wv[k*HN + (n - VOFF)];
    } else {
        int j = i - NCOLS1*D_MODEL;
        if (j < D_MODEL*HN) {
            int n = j >> 6, k = j & 63;          // g_Bt2[n][k] = Wo[k][n]
            g_Bt2[j] = Wo[k*D_MODEL + n];
        }
    }
}

// ---------------- K2: expm of 4x4 skew-symmetric ----------------
__device__ __forceinline__ void mm4(const float* __restrict__ A,
                                    const float* __restrict__ B,
                                    float* __restrict__ C) {
    #pragma unroll
    for (int i = 0; i < 4; i++)
        #pragma unroll
        for (int j = 0; j < 4; j++)
            C[i*4+j] = A[i*4+0]*B[0*4+j] + A[i*4+1]*B[1*4+j]
                     + A[i*4+2]*B[2*4+j] + A[i*4+3]*B[3*4+j];
}

__global__ void expm_kernel() {
    int tid = blockIdx.x*blockDim.x + threadIdx.x;   // chain-major: chain*Tt + t
    if (tid >= CHAINS*Tt) return;
    int t     = tid & (Tt-1);
    int chain = tid >> 12;
    int b     = chain >> 4;
    int h     = chain & 15;
    int n     = b*Tt + t;

    const float* s = g_SV + (size_t)n*NCOLS1 + h*NSKEW;
    float a01 = s[0], a02 = s[1], a03 = s[2], a12 = s[3], a13 = s[4], a23 = s[5];

    float fr = sqrtf(2.0f*(a01*a01 + a02*a02 + a03*a03 +
                           a12*a12 + a13*a13 + a23*a23));
    int sft = 0;
    float f = fr;
    while (f > 0.25f && sft < 32) { f *= 0.5f; sft++; }
    float sc = ldexpf(1.0f, -sft);

    float A[16] = {  0.f,  a01,  a02,  a03,
                    -a01,  0.f,  a12,  a13,
                    -a02, -a12,  0.f,  a23,
                    -a03, -a13, -a23,  0.f };
    #pragma unroll
    for (int e = 0; e < 16; e++) A[e] *= sc;

    float Tm[16], Tmp[16];
    #pragma unroll
    for (int e = 0; e < 16; e++)
        Tm[e] = A[e]*(1.0f/8.0f) + ((e % 5 == 0) ? 1.0f : 0.0f);
    #pragma unroll
    for (int k = 7; k >= 1; k--) {
        mm4(A, Tm, Tmp);
        float inv = 1.0f/(float)k;
        #pragma unroll
        for (int e = 0; e < 16; e++)
            Tm[e] = Tmp[e]*inv + ((e % 5 == 0) ? 1.0f : 0.0f);
    }
    for (int q = 0; q < sft; q++) {
        mm4(Tm, Tm, Tmp);
        #pragma unroll
        for (int e = 0; e < 16; e++) Tm[e] = Tmp[e];
    }

    float4* out = (float4*)(g_R + (size_t)tid*16);
    out[0] = make_float4(Tm[0],  Tm[1],  Tm[2],  Tm[3]);
    out[1] = make_float4(Tm[4],  Tm[5],  Tm[6],  Tm[7]);
    out[2] = make_float4(Tm[8],  Tm[9],  Tm[10], Tm[11]);
    out[3] = make_float4(Tm[12], Tm[13], Tm[14], Tm[15]);
}

// ---------------- K3: chunk-local prefix products ----------------
// 4 threads per (chain, chunk); thread `lane` owns column `lane`.
__global__ void scan_local_kernel() {
    int gtid  = blockIdx.x*blockDim.x + threadIdx.x;
    int lane  = gtid & 3;
    int g     = gtid >> 2;
    if (g >= CHAINS*NCHUNK) return;
    int chunk = g & (NCHUNK-1);
    int chain = g >> 8;                    // NCHUNK == 256

    const float4* Rb = (const float4*)(g_R + ((size_t)chain*Tt + chunk*CHUNK)*16);
    float* Lb        = g_L + ((size_t)chain*Tt + chunk*CHUNK)*16;

    float m0 = (lane==0), m1 = (lane==1), m2 = (lane==2), m3 = (lane==3);
    #pragma unroll 4
    for (int t = 0; t < CHUNK; t++) {
        float4 r0 = Rb[t*4+0], r1 = Rb[t*4+1], r2 = Rb[t*4+2], r3 = Rb[t*4+3];
        float n0 = r0.x*m0 + r0.y*m1 + r0.z*m2 + r0.w*m3;
        float n1 = r1.x*m0 + r1.y*m1 + r1.z*m2 + r1.w*m3;
        float n2 = r2.x*m0 + r2.y*m1 + r2.z*m2 + r2.w*m3;
        float n3 = r3.x*m0 + r3.y*m1 + r3.z*m2 + r3.w*m3;
        m0 = n0; m1 = n1; m2 = n2; m3 = n3;
        Lb[t*16 +  0 + lane] = m0;
        Lb[t*16 +  4 + lane] = m1;
        Lb[t*16 +  8 + lane] = m2;
        Lb[t*16 + 12 + lane] = m3;
    }
    float* Cb = g_Ctot + ((size_t)chain*NCHUNK + chunk)*16;
    Cb[ 0 + lane] = m0; Cb[ 4 + lane] = m1;
    Cb[ 8 + lane] = m2; Cb[12 + lane] = m3;
}

// ---------------- K4: Kogge-Stone scan over chunk totals (per chain) ----------------
// 64 blocks (one per chain) x 256 threads (one per chunk).
__global__ void __launch_bounds__(NCHUNK) prefix_kernel() {
    __shared__ float sm[NCHUNK*17];
    const int i     = threadIdx.x;
    const int chain = blockIdx.x;

    float M[16];
    const float* Cb = g_Ctot + ((size_t)chain*NCHUNK + i)*16;
    #pragma unroll
    for (int e = 0; e < 16; e++) M[e] = Cb[e];

    #pragma unroll
    for (int d = 1; d < NCHUNK; d <<= 1) {
        #pragma unroll
        for (int e = 0; e < 16; e++) sm[i*17 + e] = M[e];
        __syncthreads();
        if (i >= d) {
            float P[16], T[16];
            #pragma unroll
            for (int e = 0; e < 16; e++) P[e] = sm[(i-d)*17 + e];
            mm4(M, P, T);                       // newer (M) on the left
            #pragma unroll
            for (int e = 0; e < 16; e++) M[e] = T[e];
        }
        __syncthreads();
    }

    // exclusive shift: P_prev[i] = inclusive[i-1], P_prev[0] = I
    #pragma unroll
    for (int e = 0; e < 16; e++) sm[i*17 + e] = M[e];
    __syncthreads();
    float* Pb = g_Pprev + ((size_t)chain*NCHUNK + i)*16;
    if (i == 0) {
        #pragma unroll
        for (int e = 0; e < 16; e++) Pb[e] = (e % 5 == 0) ? 1.0f : 0.0f;
    } else {
        #pragma unroll
        for (int e = 0; e < 16; e++) Pb[e] = sm[(i-1)*17 + e];
    }
}

// ---------------- K5: rotated[t] = local[t] @ (P_prev @ v[t]) ----------------
__global__ void rotate_kernel() {
    int tid = blockIdx.x*blockDim.x + threadIdx.x;
    if (tid >= CHAINS*Tt) return;
    int t     = tid & (Tt-1);
    int chain = tid >> 12;
    int b     = chain >> 4;
    int h     = chain & 15;
    int n     = b*Tt + t;
    int chunk = t >> 4;                    // CHUNK == 16

    float4 v = *(const float4*)(g_SV + (size_t)n*NCOLS1 + VOFF + h*Nn);
    const float* P = g_Pprev + ((size_t)chain*NCHUNK + chunk)*16;
    float u0 = P[ 0]*v.x + P[ 1]*v.y + P[ 2]*v.z + P[ 3]*v.w;
    float u1 = P[ 4]*v.x + P[ 5]*v.y + P[ 6]*v.z + P[ 7]*v.w;
    float u2 = P[ 8]*v.x + P[ 9]*v.y + P[10]*v.z + P[11]*v.w;
    float u3 = P[12]*v.x + P[13]*v.y + P[14]*v.z + P[15]*v.w;

    const float4* L = (const float4*)(g_L + (size_t)tid*16);
    float4 l0 = L[0], l1 = L[1], l2 = L[2], l3 = L[3];
    float r0 = l0.x*u0 + l0.y*u1 + l0.z*u2 + l0.w*u3;
    float r1 = l1.x*u0 + l1.y*u1 + l1.z*u2 + l1.w*u3;
    float r2 = l2.x*u0 + l2.y*u1 + l2.z*u2 + l2.w*u3;
    float r3 = l3.x*u0 + l3.y*u1 + l3.z*u2 + l3.w*u3;

    *(float4*)(g_Rot + (size_t)n*HN + h*Nn) = make_float4(r0, r1, r2, r3);
}

// ---------------- launcher ----------------
extern "C" void kernel_launch(void* const* d_in, const int* in_sizes, int n_in,
                              void* d_out, int out_size) {
    const float* x     = (const float*)d_in[0];
    const float* Wskew = (const float*)d_in[1];
    const float* Wv    = (const float*)d_in[2];
    const float* Wo    = (const float*)d_in[3];
    float* out = (float*)d_out;

    float *g_Bt1_p, *g_Bt2_p, *g_SV_p, *g_Rot_p;
    cudaGetSymbolAddress((void**)&g_Bt1_p, g_Bt1);
    cudaGetSymbolAddress((void**)&g_Bt2_p, g_Bt2);
    cudaGetSymbolAddress((void**)&g_SV_p,  g_SV);
    cudaGetSymbolAddress((void**)&g_Rot_p, g_Rot);

    prep_kernel<<<(NCOLS1*D_MODEL + D_MODEL*HN + 255)/256, 256>>>(Wskew, Wv, Wo);
    gemm_bf16_kernel<NCOLS1, NCOLS1, D_MODEL>
        <<<dim3(1, NROWS/128), 256>>>(x, g_Bt1_p, g_SV_p);
    expm_kernel<<<(CHAINS*Tt)/256, 256>>>();
    scan_local_kernel<<<(CHAINS*NCHUNK*4)/256, 256>>>();
    prefix_kernel<<<CHAINS, NCHUNK>>>();
    rotate_kernel<<<(CHAINS*Tt)/256, 256>>>();
    gemm_bf16_kernel<128, D_MODEL, HN>
        <<<dim3(D_MODEL/128, NROWS/128), 256>>>(g_Rot_p, g_Bt2_p, out);
}

// round 6
// speedup vs baseline: 2.6847x; 1.0380x over previous
#include <cuda_runtime.h>
#include <cuda_bf16.h>
#include <cstdint>

// ---------------- problem constants ----------------
#define D_MODEL 1024
#define Hh      16
#define Nn      4
#define NSKEW   6
#define Bb      4
#define Tt      4096
#define NROWS   (Bb*Tt)                    // 16384
#define NCOLS1  (Hh*NSKEW + Hh*Nn)         // 160
#define VOFF    (Hh*NSKEW)                 // 96
#define HN      (Hh*Nn)                    // 64
#define CHAINS  (Bb*Hh)                    // 64
#define CHUNK   8
#define NCHUNK  (Tt/CHUNK)                 // 512

// ---------------- scratch ----------------
__device__ float g_Bt1 [NCOLS1*D_MODEL];        // Wcat^T  (160 x 1024)
__device__ float g_Bt2 [D_MODEL*HN];            // Wo^T    (1024 x 64)
__device__ float g_SV  [NROWS*NCOLS1];
__device__ float g_L   [CHAINS*Tt*16];
__device__ float g_Ctot[CHAINS*NCHUNK*16];
__device__ float g_Pprev[CHAINS*NCHUNK*16];
__device__ float g_Rot [NROWS*HN];

// ---------------- bf16 helpers ----------------
__device__ __forceinline__ void mma_bf16(float* c,
                                         uint32_t a0, uint32_t a1, uint32_t a2, uint32_t a3,
                                         uint32_t b0, uint32_t b1) {
    asm volatile(
        "mma.sync.aligned.m16n8k16.row.col.f32.bf16.bf16.f32 "
        "{%0,%1,%2,%3}, {%4,%5,%6,%7}, {%8,%9}, {%0,%1,%2,%3};"
        : "+f"(c[0]), "+f"(c[1]), "+f"(c[2]), "+f"(c[3])
        : "r"(a0), "r"(a1), "r"(a2), "r"(a3), "r"(b0), "r"(b1));
}

__device__ __forceinline__ void split_pack(float4 v, uint2& hi, uint2& lo) {
    __nv_bfloat16 hx = __float2bfloat16_rn(v.x);
    __nv_bfloat16 hy = __float2bfloat16_rn(v.y);
    __nv_bfloat16 hz = __float2bfloat16_rn(v.z);
    __nv_bfloat16 hw = __float2bfloat16_rn(v.w);
    __nv_bfloat16 lx = __float2bfloat16_rn(v.x - __bfloat162float(hx));
    __nv_bfloat16 ly = __float2bfloat16_rn(v.y - __bfloat162float(hy));
    __nv_bfloat16 lz = __float2bfloat16_rn(v.z - __bfloat162float(hz));
    __nv_bfloat16 lw = __float2bfloat16_rn(v.w - __bfloat162float(hw));
    hi.x = (uint32_t)__bfloat16_as_ushort(hx) | ((uint32_t)__bfloat16_as_ushort(hy) << 16);
    hi.y = (uint32_t)__bfloat16_as_ushort(hz) | ((uint32_t)__bfloat16_as_ushort(hw) << 16);
    lo.x = (uint32_t)__bfloat16_as_ushort(lx) | ((uint32_t)__bfloat16_as_ushort(ly) << 16);
    lo.y = (uint32_t)__bfloat16_as_ushort(lz) | ((uint32_t)__bfloat16_as_ushort(lw) << 16);
}

// ---------------- bf16-split HMMA GEMM (double-buffered) ----------------
// C[M,NTOT] = A[M,KTOT] @ Bt[NTOT,KTOT]^T  (fp32 row-major everywhere).
// BM=128 rows/CTA, BN cols/CTA, K stepped by 16. 8 warps 4(m)x2(n).
// Two smem stages, one __syncthreads per k-step; global loads for step s+1
// are issued before the compute of step s.
template<int BN, int NTOT, int KTOT>
__global__ void __launch_bounds__(256) gemm_bf16_kernel(const float* __restrict__ A,
                                                        const float* __restrict__ Bt,
                                                        float* __restrict__ C) {
    constexpr int BM = 128, KC = 16;
    constexpr int NSTEP = KTOT / KC;
    constexpr int WM = 32;                  // BM/4
    constexpr int WN = BN / 2;
    constexpr int MT = 2;
    constexpr int NT = WN / 8;
    constexpr int RS = 48;                  // 32B bf16 data + 16B pad (conflict-free)
    constexpr int STG = (2*BM + 2*BN) * RS; // bytes per stage
    constexpr int AHI = 0;
    constexpr int ALO = BM * RS;
    constexpr int BHI = 2 * BM * RS;
    constexpr int BLO = 2 * BM * RS + BN * RS;
    constexpr int NF4 = (BM + BN) * 4;
    constexpr int MAXR = (NF4 + 255) / 256;

    extern __shared__ __align__(16) unsigned char smem[];

    const int tid  = threadIdx.x;
    const int warp = tid >> 5;
    const int lane = tid & 31;
    const int brow = blockIdx.y * BM;
    const int bcol = blockIdx.x * BN;
    const int wm0  = (warp >> 1) * WM;
    const int wn0  = (warp & 1) * WN;
    const int gr   = lane >> 2;
    const int lc   = lane & 3;

    float acc[MT][NT][4];
    #pragma unroll
    for (int i = 0; i < MT; i++)
        #pragma unroll
        for (int j = 0; j < NT; j++)
            #pragma unroll
            for (int e = 0; e < 4; e++) acc[i][j][e] = 0.f;

    // per-thread load slots (fixed across steps)
    int srow[MAXR], sq[MAXR], sdh[MAXR], sdl[MAXR];
    bool sA[MAXR], valid[MAXR];
    #pragma unroll
    for (int r = 0; r < MAXR; r++) {
        int e = tid + r*256;
        valid[r] = (e < NF4);
        if (e < BM*4) { srow[r] = e >> 2; sq[r] = e & 3; sdh[r] = AHI; sdl[r] = ALO; sA[r] = true; }
        else { int e2 = e - BM*4; srow[r] = e2 >> 2; sq[r] = e2 & 3; sdh[r] = BHI; sdl[r] = BLO; sA[r] = false; }
    }

    float4 pf[MAXR];
    // prologue: chunk 0 -> regs -> stage 0
    #pragma unroll
    for (int r = 0; r < MAXR; r++) if (valid[r])
        pf[r] = sA[r] ? *(const float4*)(A  + (size_t)(brow + srow[r])*KTOT + sq[r]*4)
                      : *(const float4*)(Bt + (size_t)(bcol + srow[r])*KTOT + sq[r]*4);
    #pragma unroll
    for (int r = 0; r < MAXR; r++) if (valid[r]) {
        uint2 hi, lo; split_pack(pf[r], hi, lo);
        *(uint2*)&smem[sdh[r] + srow[r]*RS + sq[r]*8] = hi;
        *(uint2*)&smem[sdl[r] + srow[r]*RS + sq[r]*8] = lo;
    }

    for (int s = 0; s < NSTEP; s++) {
        __syncthreads();                    // stage s%2 fully written
        const unsigned char* cur = smem + (s & 1) * STG;
        // issue next chunk's global loads (latency hides under MMAs)
        if (s + 1 < NSTEP) {
            #pragma unroll
            for (int r = 0; r < MAXR; r++) if (valid[r])
                pf[r] = sA[r] ? *(const float4*)(A  + (size_t)(brow + srow[r])*KTOT + (s+1)*KC + sq[r]*4)
                              : *(const float4*)(Bt + (size_t)(bcol + srow[r])*KTOT + (s+1)*KC + sq[r]*4);
        }
        // ---- compute on stage s%2 ----
        uint32_t ah[MT][4], al[MT][4];
        #pragma unroll
        for (int mt = 0; mt < MT; mt++) {
            int ro = (wm0 + mt*16 + gr) * RS + lc*4;
            ah[mt][0] = *(const uint32_t*)&cur[AHI + ro];
            ah[mt][1] = *(const uint32_t*)&cur[AHI + ro + 8*RS];
            ah[mt][2] = *(const uint32_t*)&cur[AHI + ro + 16];
            ah[mt][3] = *(const uint32_t*)&cur[AHI + ro + 8*RS + 16];
            al[mt][0] = *(const uint32_t*)&cur[ALO + ro];
            al[mt][1] = *(const uint32_t*)&cur[ALO + ro + 8*RS];
            al[mt][2] = *(const uint32_t*)&cur[ALO + ro + 16];
            al[mt][3] = *(const uint32_t*)&cur[ALO + ro + 8*RS + 16];
        }
        #pragma unroll
        for (int nt = 0; nt < NT; nt++) {
            int ro = (wn0 + nt*8 + gr) * RS + lc*4;
            uint32_t bh0 = *(const uint32_t*)&cur[BHI + ro];
            uint32_t bh1 = *(const uint32_t*)&cur[BHI + ro + 16];
            uint32_t bl0 = *(const uint32_t*)&cur[BLO + ro];
            uint32_t bl1 = *(const uint32_t*)&cur[BLO + ro + 16];
            #pragma unroll
            for (int mt = 0; mt < MT; mt++) {
                mma_bf16(acc[mt][nt], ah[mt][0], ah[mt][1], ah[mt][2], ah[mt][3], bh0, bh1);
                mma_bf16(acc[mt][nt], al[mt][0], al[mt][1], al[mt][2], al[mt][3], bh0, bh1);
                mma_bf16(acc[mt][nt], ah[mt][0], ah[mt][1], ah[mt][2], ah[mt][3], bl0, bl1);
            }
        }
        // store next chunk into the other stage (no sync needed: that stage was
        // last READ in step s-1, which completed before this step's barrier)
        if (s + 1 < NSTEP) {
            unsigned char* nxt = smem + ((s + 1) & 1) * STG;
            #pragma unroll
            for (int r = 0; r < MAXR; r++) if (valid[r]) {
                uint2 hi, lo; split_pack(pf[r], hi, lo);
                *(uint2*)&nxt[sdh[r] + srow[r]*RS + sq[r]*8] = hi;
                *(uint2*)&nxt[sdl[r] + srow[r]*RS + sq[r]*8] = lo;
            }
        }
    }

    // ---- epilogue ----
    #pragma unroll
    for (int mt = 0; mt < MT; mt++) {
        int r0 = brow + wm0 + mt*16 + gr;
        #pragma unroll
        for (int nt = 0; nt < NT; nt++) {
            int c0 = bcol + wn0 + nt*8 + 2*lc;
            *(float2*)(C + (size_t)r0*NTOT + c0)       = make_float2(acc[mt][nt][0], acc[mt][nt][1]);
            *(float2*)(C + (size_t)(r0 + 8)*NTOT + c0) = make_float2(acc[mt][nt][2], acc[mt][nt][3]);
        }
    }
}

// ---------------- K0: transpose/concat weights ----------------
__global__ void prep_kernel(const float* __restrict__ Wskew,
                            const float* __restrict__ Wv,
                            const float* __restrict__ Wo) {
    int i = blockIdx.x*blockDim.x + threadIdx.x;
    if (i < NCOLS1*D_MODEL) {
        int n = i >> 10, k = i & 1023;           // g_Bt1[n][k] = Wcat[k][n]
        g_Bt1[i] = (n < VOFF) ? Wskew[k*VOFF + n] : Wv[k*HN + (n - VOFF)];
    } else {
        int j = i - NCOLS1*D_MODEL;
        if (j < D_MODEL*HN) {
            int n = j >> 6, k = j & 63;          // g_Bt2[n][k] = Wo[k][n]
            g_Bt2[j] = Wo[k*D_MODEL + n];
        }
    }
}

// ---------------- mm4 ----------------
__device__ __forceinline__ void mm4(const float* __restrict__ A,
                                    const float* __restrict__ B,
                                    float* __restrict__ C) {
    #pragma unroll
    for (int i = 0; i < 4; i++)
        #pragma unroll
        for (int j = 0; j < 4; j++)
            C[i*4+j] = A[i*4+0]*B[0*4+j] + A[i*4+1]*B[1*4+j]
                     + A[i*4+2]*B[2*4+j] + A[i*4+3]*B[3*4+j];
}

// ---------------- K2: fused expm + chunk-local scan ----------------
// One thread per (chain, chunk): computes R_t = expm(skew_t) inline and folds
// it into the running left-product; writes local prefixes + chunk total.
// Eliminates the g_R buffer entirely.
__global__ void __launch_bounds__(256) expm_scan_kernel() {
    int g = blockIdx.x*blockDim.x + threadIdx.x;
    if (g >= CHAINS*NCHUNK) return;
    int chunk = g & (NCHUNK-1);
    int chain = g >> 9;                    // NCHUNK == 512
    int b     = chain >> 4;
    int h     = chain & 15;
    int t0    = chunk * CHUNK;

    const float* sv = g_SV + (size_t)(b*Tt + t0)*NCOLS1 + h*NSKEW;
    float* Lb = g_L + ((size_t)chain*Tt + t0)*16;

    float m[16];
    #pragma unroll
    for (int e = 0; e < 16; e++) m[e] = (e % 5 == 0) ? 1.0f : 0.0f;

    for (int t = 0; t < CHUNK; t++) {
        float2 s01 = *(const float2*)(sv + (size_t)t*NCOLS1);
        float2 s23 = *(const float2*)(sv + (size_t)t*NCOLS1 + 2);
        float2 s45 = *(const float2*)(sv + (size_t)t*NCOLS1 + 4);
        float a01 = s01.x, a02 = s01.y, a03 = s23.x;
        float a12 = s23.y, a13 = s45.x, a23 = s45.y;

        float fr = sqrtf(2.0f*(a01*a01 + a02*a02 + a03*a03 +
                               a12*a12 + a13*a13 + a23*a23));
        int sft = 0;
        float f = fr;
        while (f > 0.25f && sft < 32) { f *= 0.5f; sft++; }
        float sc = ldexpf(1.0f, -sft);

        float A[16] = {  0.f,  a01,  a02,  a03,
                        -a01,  0.f,  a12,  a13,
                        -a02, -a12,  0.f,  a23,
                        -a03, -a13, -a23,  0.f };
        #pragma unroll
        for (int e = 0; e < 16; e++) A[e] *= sc;

        float Tm[16], Tmp[16];
        #pragma unroll
        for (int e = 0; e < 16; e++)
            Tm[e] = A[e]*(1.0f/8.0f) + ((e % 5 == 0) ? 1.0f : 0.0f);
        #pragma unroll
        for (int k = 7; k >= 1; k--) {
            mm4(A, Tm, Tmp);
            float inv = 1.0f/(float)k;
            #pragma unroll
            for (int e = 0; e < 16; e++)
                Tm[e] = Tmp[e]*inv + ((e % 5 == 0) ? 1.0f : 0.0f);
        }
        for (int q = 0; q < sft; q++) {
            mm4(Tm, Tm, Tmp);
            #pragma unroll
            for (int e = 0; e < 16; e++) Tm[e] = Tmp[e];
        }

        // m = R_t @ m
        float nm[16];
        mm4(Tm, m, nm);
        #pragma unroll
        for (int e = 0; e < 16; e++) m[e] = nm[e];

        float4* Lo = (float4*)(Lb + (size_t)t*16);
        Lo[0] = make_float4(m[0],  m[1],  m[2],  m[3]);
        Lo[1] = make_float4(m[4],  m[5],  m[6],  m[7]);
        Lo[2] = make_float4(m[8],  m[9],  m[10], m[11]);
        Lo[3] = make_float4(m[12], m[13], m[14], m[15]);
    }

    float4* Cb = (float4*)(g_Ctot + ((size_t)chain*NCHUNK + chunk)*16);
    Cb[0] = make_float4(m[0],  m[1],  m[2],  m[3]);
    Cb[1] = make_float4(m[4],  m[5],  m[6],  m[7]);
    Cb[2] = make_float4(m[8],  m[9],  m[10], m[11]);
    Cb[3] = make_float4(m[12], m[13], m[14], m[15]);
}

// ---------------- K4: Kogge-Stone scan over chunk totals (per chain) ----------------
// 64 blocks (one per chain) x 512 threads (one per chunk), 9 stages.
__global__ void __launch_bounds__(NCHUNK) prefix_kernel() {
    __shared__ float sm[NCHUNK*17];
    const int i     = threadIdx.x;
    const int chain = blockIdx.x;

    float M[16];
    const float* Cb = g_Ctot + ((size_t)chain*NCHUNK + i)*16;
    #pragma unroll
    for (int e = 0; e < 16; e++) M[e] = Cb[e];

    #pragma unroll
    for (int d = 1; d < NCHUNK; d <<= 1) {
        #pragma unroll
        for (int e = 0; e < 16; e++) sm[i*17 + e] = M[e];
        __syncthreads();
        if (i >= d) {
            float P[16], T[16];
            #pragma unroll
            for (int e = 0; e < 16; e++) P[e] = sm[(i-d)*17 + e];
            mm4(M, P, T);                       // newer (M) on the left
            #pragma unroll
            for (int e = 0; e < 16; e++) M[e] = T[e];
        }
        __syncthreads();
    }

    // exclusive shift: P_prev[i] = inclusive[i-1], P_prev[0] = I
    #pragma unroll
    for (int e = 0; e < 16; e++) sm[i*17 + e] = M[e];
    __syncthreads();
    float* Pb = g_Pprev + ((size_t)chain*NCHUNK + i)*16;
    if (i == 0) {
        #pragma unroll
        for (int e = 0; e < 16; e++) Pb[e] = (e % 5 == 0) ? 1.0f : 0.0f;
    } else {
        #pragma unroll
        for (int e = 0; e < 16; e++) Pb[e] = sm[(i-1)*17 + e];
    }
}

// ---------------- K5: rotated[t] = local[t] @ (P_prev @ v[t]) ----------------
__global__ void rotate_kernel() {
    int tid = blockIdx.x*blockDim.x + threadIdx.x;
    if (tid >= CHAINS*Tt) return;
    int t     = tid & (Tt-1);
    int chain = tid >> 12;
    int b     = chain >> 4;
    int h     = chain & 15;
    int n     = b*Tt + t;
    int chunk = t >> 3;                    // CHUNK == 8

    float4 v = *(const float4*)(g_SV + (size_t)n*NCOLS1 + VOFF + h*Nn);
    const float* P = g_Pprev + ((size_t)chain*NCHUNK + chunk)*16;
    float u0 = P[ 0]*v.x + P[ 1]*v.y + P[ 2]*v.z + P[ 3]*v.w;
    float u1 = P[ 4]*v.x + P[ 5]*v.y + P[ 6]*v.z + P[ 7]*v.w;
    float u2 = P[ 8]*v.x + P[ 9]*v.y + P[10]*v.z + P[11]*v.w;
    float u3 = P[12]*v.x + P[13]*v.y + P[14]*v.z + P[15]*v.w;

    const float* L = g_L + (size_t)tid*16;
    float4 l0 = *(const float4*)(L);
    float4 l1 = *(const float4*)(L + 4);
    float4 l2 = *(const float4*)(L + 8);
    float4 l3 = *(const float4*)(L + 12);
    float r0 = l0.x*u0 + l0.y*u1 + l0.z*u2 + l0.w*u3;
    float r1 = l1.x*u0 + l1.y*u1 + l1.z*u2 + l1.w*u3;
    float r2 = l2.x*u0 + l2.y*u1 + l2.z*u2 + l2.w*u3;
    float r3 = l3.x*u0 + l3.y*u1 + l3.z*u2 + l3.w*u3;

    *(float4*)(g_Rot + (size_t)n*HN + h*Nn) = make_float4(r0, r1, r2, r3);
}

// ---------------- launcher ----------------
extern "C" void kernel_launch(void* const* d_in, const int* in_sizes, int n_in,
                              void* d_out, int out_size) {
    const float* x     = (const float*)d_in[0];
    const float* Wskew = (const float*)d_in[1];
    const float* Wv    = (const float*)d_in[2];
    const float* Wo    = (const float*)d_in[3];
    float* out = (float*)d_out;

    float *g_Bt1_p, *g_Bt2_p, *g_SV_p, *g_Rot_p;
    cudaGetSymbolAddress((void**)&g_Bt1_p, g_Bt1);
    cudaGetSymbolAddress((void**)&g_Bt2_p, g_Bt2);
    cudaGetSymbolAddress((void**)&g_SV_p,  g_SV);
    cudaGetSymbolAddress((void**)&g_Rot_p, g_Rot);

    const int SM1 = 2 * (2*128 + 2*NCOLS1) * 48;   // 55296 B
    const int SM2 = 2 * (2*128 + 2*128) * 48;      // 49152 B
    cudaFuncSetAttribute(gemm_bf16_kernel<NCOLS1, NCOLS1, D_MODEL>,
                         cudaFuncAttributeMaxDynamicSharedMemorySize, SM1);
    cudaFuncSetAttribute(gemm_bf16_kernel<128, D_MODEL, HN>,
                         cudaFuncAttributeMaxDynamicSharedMemorySize, SM2);

    prep_kernel<<<(NCOLS1*D_MODEL + D_MODEL*HN + 255)/256, 256>>>(Wskew, Wv, Wo);
    gemm_bf16_kernel<NCOLS1, NCOLS1, D_MODEL>
        <<<dim3(1, NROWS/128), 256, SM1>>>(x, g_Bt1_p, g_SV_p);
    expm_scan_kernel<<<(CHAINS*NCHUNK + 255)/256, 256>>>();
    prefix_kernel<<<CHAINS, NCHUNK>>>();
    rotate_kernel<<<(CHAINS*Tt)/256, 256>>>();
    gemm_bf16_kernel<128, D_MODEL, HN>
        <<<dim3(D_MODEL/128, NROWS/128), 256, SM2>>>(g_Rot_p, g_Bt2_p, out);
}